// round 4
// baseline (speedup 1.0000x reference)
#include <cuda_runtime.h>
#include <cuda_bf16.h>
#include <cstdint>

// Problem constants
#define Bn 64
#define Tn 64
#define Dn 64
#define Pn 63   // prefixes 0..62

typedef unsigned long long ull;

// ---------------- device scratch ----------------
__device__ float g_emb[Tn * Bn * 128];           // [t][b][e]
__device__ float g_gia[Tn * Bn * 384];           // [t][b][u]  u = gate*128+k (r,z,n)
__device__ float g_gib[Tn * Bn * 384];
__device__ float g_WhaT[128 * 384];              // [i][u] = Wh_a[u][i]
__device__ float g_WhbT[128 * 384];
__device__ float g_WiaT[128 * 384];              // [e][u] = Wi_a[u][e]
__device__ float g_WibT[128 * 384];
__device__ float g_WbT[128 * 128];               // [i][e] = Wb[e][i]
__device__ float g_WembT[64 * 128];              // [d][e] = W_emb[e][d]
__device__ float g_WoWemb[128 * 64];             // [e][d] = Wo[e]*W_emb[e][d]

// ---------------- f32x2 helpers ----------------
__device__ __forceinline__ ull pack2(float x, float y) {
    ull r;
    asm("mov.b64 %0, {%1,%2};" : "=l"(r) : "f"(x), "f"(y));
    return r;
}
__device__ __forceinline__ float2 unpack2(ull v) {
    float2 r;
    asm("mov.b64 {%0,%1}, %2;" : "=f"(r.x), "=f"(r.y) : "l"(v));
    return r;
}
__device__ __forceinline__ ull fma2(ull a, ull b, ull c) {
    ull d;
    asm("fma.rn.f32x2 %0, %1, %2, %3;" : "=l"(d) : "l"(a), "l"(b), "l"(c));
    return d;
}

__device__ __forceinline__ float sigmoidf_(float v) {
    return __fdividef(1.f, 1.f + __expf(-v));
}
__device__ __forceinline__ float tanhfast(float v) {
    float e = __expf(2.f * v);
    return 1.f - __fdividef(2.f, e + 1.f);
}
__device__ __forceinline__ float gru_step(float ir, float iz, float in_,
                                          float hr, float hz, float hn, float h) {
    float r = sigmoidf_(ir + hr);
    float z = sigmoidf_(iz + hz);
    float n = tanhfast(in_ + r * hn);
    return n + z * (h - n);
}

// ---------------- prep: transposes ----------------
__global__ void prep_transpose(const float* __restrict__ Wh_a,
                               const float* __restrict__ Wh_b,
                               const float* __restrict__ Wi_a,
                               const float* __restrict__ Wi_b,
                               const float* __restrict__ Wb,
                               const float* __restrict__ W_emb,
                               const float* __restrict__ Wo) {
    int idx = blockIdx.x * blockDim.x + threadIdx.x;
    int stride = gridDim.x * blockDim.x;
    for (int n = idx; n < 128 * 384; n += stride) {
        int u = n % 384, i = n / 384;
        g_WhaT[n] = Wh_a[u * 128 + i];
        g_WhbT[n] = Wh_b[u * 128 + i];
        g_WiaT[n] = Wi_a[u * 128 + i];
        g_WibT[n] = Wi_b[u * 128 + i];
    }
    for (int n = idx; n < 128 * 128; n += stride) {
        int e = n % 128, i = n / 128;
        g_WbT[n] = Wb[e * 128 + i];
    }
    for (int n = idx; n < 64 * 128; n += stride) {
        int e = n % 128, d = n / 128;
        g_WembT[n] = W_emb[e * 64 + d];
    }
    for (int n = idx; n < 128 * 64; n += stride) {
        int d = n % 64, e = n / 64;
        g_WoWemb[n] = Wo[e] * W_emb[e * 64 + d];
    }
}

// ---------------- emb ----------------
__global__ void emb_kernel(const float* __restrict__ x, const float* __restrict__ b_emb) {
    __shared__ float xs[64];
    int tb = blockIdx.x;
    int t_ = tb >> 6, b = tb & 63;
    int e = threadIdx.x;
    if (e < 64) xs[e] = x[((size_t)b * Tn + t_) * Dn + e];
    __syncthreads();
    float acc = 0.f;
#pragma unroll 8
    for (int d = 0; d < 64; ++d) acc = fmaf(g_WembT[d * 128 + e], xs[d], acc);
    g_emb[(size_t)tb * 128 + e] = acc + b_emb[e];
}

// ---------------- gi ----------------
__global__ void gi_kernel(const float* __restrict__ bi_a, const float* __restrict__ bi_b) {
    __shared__ float es[128];
    int tb = blockIdx.x;
    int t = threadIdx.x;
    if (t < 128) es[t] = g_emb[(size_t)tb * 128 + t];
    __syncthreads();
    for (int u = t; u < 768; u += 256) {
        const float* WT;
        const float* bi;
        float* out;
        int uu;
        if (u < 384) { WT = g_WiaT; bi = bi_a; out = g_gia; uu = u; }
        else         { WT = g_WibT; bi = bi_b; out = g_gib; uu = u - 384; }
        float acc = 0.f;
#pragma unroll 8
        for (int e = 0; e < 128; ++e) acc = fmaf(WT[e * 384 + uu], es[e], acc);
        out[(size_t)tb * 384 + uu] = acc + bi[uu];
    }
}

// ---------------- main persistent kernel ----------------
// grid: 128 blocks = 32 prefix-pairs x 4 batch-chunks of 16 rows.
// block pb handles prefix 62-pb, then prefix pb (pb<31). ~64 iters each.
__global__ __launch_bounds__(256, 1) void retain_main(
    const float* __restrict__ x,
    const float* __restrict__ bh_a, const float* __restrict__ bh_b,
    const float* __restrict__ Wa, const float* __restrict__ ba,
    const float* __restrict__ bb, const float* __restrict__ Wo,
    const float* __restrict__ bo, int nq, float* __restrict__ out) {

    __shared__ ull sh_h[2][2][128][8];   // [buf][gru][i][rp], rp packs rows (2rp,2rp+1). 32KB
    __shared__ ull sh_betaP[8][128];     // beta packed by row-pair. 8KB
    __shared__ float sh_preA[16], sh_scale[16], sh_w[16], sh_m[16], sh_l[16];

    const int t = threadIdx.x;
    const int pb = blockIdx.x >> 2;
    const int b0 = (blockIdx.x & 3) * 16;

    const int gru = t >> 7;        // 0/1: which GRU this half computes
    const int k = t & 127;         // hidden/e index
    const int d_ = t & 63;         // x-feature index
    const int g_ = t >> 6;         // 0..3 groups of 4 rows
    const int row16 = t >> 4;      // 0..15 rows (preA mapping)
    const int l16 = t & 15;

    const float* WT  = gru ? g_WhbT : g_WhaT;
    const float* giT = gru ? g_gib  : g_gia;
    const float* bh  = gru ? bh_b   : bh_a;
    const float bhr = bh[k], bhz = bh[128 + k], bhn = bh[256 + k];
    const float ba0 = ba[0], bbk = bb[k];
    const int base = Pn - nq;      // = short + 1

    for (int seg = 0; seg < 2; ++seg) {
        const int p = seg ? pb : 62 - pb;
        if (seg && (pb >= 31 || pb < base)) break;

        // ---- init state for this trajectory ----
        for (int n = t; n < 2 * 128 * 8; n += 256)
            ((ull*)sh_h[0])[n] = 0ull;           // zero buffer 0 (s=0 reads it)
        if (t < 16) { sh_m[t] = -1e30f; sh_l[t] = 0.f; }
        float cacc[8] = {0.f, 0.f, 0.f, 0.f, 0.f, 0.f, 0.f, 0.f};
        float gacc[4] = {0.f, 0.f, 0.f, 0.f};
        __syncthreads();

        for (int s = 0; s <= p; ++s) {
            const int j = p - s;
            const int cb = s & 1;
            const ull (*cur)[8]  = sh_h[cb][gru];
            ull (*nxtg)[8]       = sh_h[cb ^ 1][gru];
            const ull (*nxtA)[8] = sh_h[cb ^ 1][0];
            const ull (*nxtB)[8] = sh_h[cb ^ 1][1];

            // ---- phase 1: gh = h @ Wh^T, 16 rows packed in 8 f32x2 pairs ----
            ull aR[8], aZ[8], aN[8];
#pragma unroll
            for (int r = 0; r < 8; ++r) { aR[r] = 0ull; aZ[r] = 0ull; aN[r] = 0ull; }
            {
                const float* W0 = WT + k;
#pragma unroll 2
                for (int i = 0; i < 128; ++i) {
                    float wr = W0[0];
                    float wz = W0[128];
                    float wn = W0[256];
                    W0 += 384;
                    ull wr2 = pack2(wr, wr), wz2 = pack2(wz, wz), wn2 = pack2(wn, wn);
                    const ulonglong2* hp = reinterpret_cast<const ulonglong2*>(cur[i]);
                    ulonglong2 hA = hp[0], hB = hp[1], hC = hp[2], hD = hp[3];
                    aR[0] = fma2(wr2, hA.x, aR[0]); aZ[0] = fma2(wz2, hA.x, aZ[0]); aN[0] = fma2(wn2, hA.x, aN[0]);
                    aR[1] = fma2(wr2, hA.y, aR[1]); aZ[1] = fma2(wz2, hA.y, aZ[1]); aN[1] = fma2(wn2, hA.y, aN[1]);
                    aR[2] = fma2(wr2, hB.x, aR[2]); aZ[2] = fma2(wz2, hB.x, aZ[2]); aN[2] = fma2(wn2, hB.x, aN[2]);
                    aR[3] = fma2(wr2, hB.y, aR[3]); aZ[3] = fma2(wz2, hB.y, aZ[3]); aN[3] = fma2(wn2, hB.y, aN[3]);
                    aR[4] = fma2(wr2, hC.x, aR[4]); aZ[4] = fma2(wz2, hC.x, aZ[4]); aN[4] = fma2(wn2, hC.x, aN[4]);
                    aR[5] = fma2(wr2, hC.y, aR[5]); aZ[5] = fma2(wz2, hC.y, aZ[5]); aN[5] = fma2(wn2, hC.y, aN[5]);
                    aR[6] = fma2(wr2, hD.x, aR[6]); aZ[6] = fma2(wz2, hD.x, aZ[6]); aN[6] = fma2(wn2, hD.x, aN[6]);
                    aR[7] = fma2(wr2, hD.y, aR[7]); aZ[7] = fma2(wz2, hD.y, aZ[7]); aN[7] = fma2(wn2, hD.y, aN[7]);
                }
            }

            // ---- phase 2: GRU cell update for 16 rows at hidden index k ----
            {
                const float* gi0 = giT + ((size_t)(j * 64 + b0)) * 384 + k;
#pragma unroll
                for (int r = 0; r < 8; ++r) {
                    float2 hr = unpack2(aR[r]);
                    float2 hz = unpack2(aZ[r]);
                    float2 hn = unpack2(aN[r]);
                    float2 ho = unpack2(cur[k][r]);
                    const float* gA = gi0 + (size_t)(2 * r) * 384;
                    const float* gB = gA + 384;
                    float hx = gru_step(gA[0], gA[128], gA[256],
                                        hr.x + bhr, hz.x + bhz, hn.x + bhn, ho.x);
                    float hy = gru_step(gB[0], gB[128], gB[256],
                                        hr.y + bhr, hz.y + bhz, hn.y + bhn, ho.y);
                    nxtg[k][r] = pack2(hx, hy);
                }
            }
            __syncthreads();

            // ---- phase 3a: beta (packed) + preA ----
            float lbeta[8];
            {
                ull bacc[4] = {0ull, 0ull, 0ull, 0ull};
                const int rpo = 4 * gru;        // this half computes beta rows 8*gru..8*gru+7
#pragma unroll 2
                for (int i = 0; i < 128; ++i) {
                    float wb = g_WbT[i * 128 + k];
                    ull wb2 = pack2(wb, wb);
                    const ulonglong2* hp =
                        reinterpret_cast<const ulonglong2*>(nxtB[i] + rpo);
                    ulonglong2 hA = hp[0], hB = hp[1];
                    bacc[0] = fma2(wb2, hA.x, bacc[0]);
                    bacc[1] = fma2(wb2, hA.y, bacc[1]);
                    bacc[2] = fma2(wb2, hB.x, bacc[2]);
                    bacc[3] = fma2(wb2, hB.y, bacc[3]);
                }
#pragma unroll
                for (int c = 0; c < 4; ++c) {
                    float2 v = unpack2(bacc[c]);
                    float bx = tanhfast(fmaf(0.5f, v.x, bbk));
                    float by = tanhfast(fmaf(0.5f, v.y, bbk));
                    lbeta[2 * c] = bx;
                    lbeta[2 * c + 1] = by;
                    sh_betaP[rpo + c][k] = pack2(bx, by);
                }
            }
            {
                float part = 0.f;
#pragma unroll
                for (int ii = 0; ii < 8; ++ii) {
                    int i = l16 + 16 * ii;
                    float2 hv = unpack2(nxtA[i][row16 >> 1]);
                    part = fmaf(Wa[i], (row16 & 1) ? hv.y : hv.x, part);
                }
#pragma unroll
                for (int o = 8; o; o >>= 1)
                    part += __shfl_xor_sync(0xffffffffu, part, o, 16);
                if (l16 == 0) sh_preA[row16] = fmaf(0.5f, part, ba0);
            }
            __syncthreads();

            // ---- phase 3b: online-softmax scalars + e_chain ----
            if (t < 16) {
                float pa = sh_preA[t], mo = sh_m[t];
                float mn = fmaxf(mo, pa);
                float sc = __expf(mo - mn);
                float w = __expf(pa - mn);
                sh_scale[t] = sc;
                sh_w[t] = w;
                sh_l[t] = sh_l[t] * sc + w;
                sh_m[t] = mn;
            }
            float ech[4];
            {
                ull ea0 = 0ull, ea1 = 0ull;
                const ull* bp0 = sh_betaP[2 * g_];
                const ull* bp1 = sh_betaP[2 * g_ + 1];
                const float* wc0 = g_WoWemb + d_;
#pragma unroll 2
                for (int e = 0; e < 128; ++e) {
                    float wc = wc0[e * 64];
                    ull wc2 = pack2(wc, wc);
                    ea0 = fma2(wc2, bp0[e], ea0);
                    ea1 = fma2(wc2, bp1[e], ea1);
                }
                float2 a = unpack2(ea0), b = unpack2(ea1);
                ech[0] = a.x; ech[1] = a.y; ech[2] = b.x; ech[3] = b.y;
            }
            __syncthreads();

            // ---- phase 3c: accumulator updates ----
            {
                const float* eb = g_emb + ((size_t)(j * 64 + b0 + 8 * gru)) * 128 + k;
#pragma unroll
                for (int c = 0; c < 8; ++c) {
                    int r = 8 * gru + c;
                    cacc[c] = fmaf(cacc[c], sh_scale[r],
                                   sh_w[r] * lbeta[c] * eb[(size_t)c * 128]);
                }
#pragma unroll
                for (int c = 0; c < 4; ++c) {
                    int r = 4 * g_ + c;
                    float xv = x[((size_t)(b0 + r) * Tn + j) * Dn + d_];
                    gacc[c] = fmaf(gacc[c], sh_scale[r], sh_w[r] * ech[c] * xv);
                }
            }
            // safe without trailing sync: next phase-1/2 touch only sh_h buffers
            // whose prior readers are ordered by the post-phase-2 barrier.
        } // steps

        // ---- finalize this trajectory ----
        __syncthreads();
        if (p >= base) {
            const int q = p - base;
            // stage context rows (packed) for the Wo reduction
#pragma unroll
            for (int c = 0; c < 4; ++c)
                sh_betaP[4 * gru + c][k] = pack2(cacc[2 * c], cacc[2 * c + 1]);
            __syncthreads();

            if (t < 16) {
                float sum = 0.f;
                const ull* Crow = sh_betaP[t >> 1];
                const bool hi = (t & 1);
#pragma unroll 8
                for (int e = 0; e < 128; ++e) {
                    float2 v = unpack2(Crow[e]);
                    sum = fmaf(Wo[e], hi ? v.y : v.x, sum);
                }
                out[(size_t)(b0 + t) * nq + q] = __fdividef(sum, sh_l[t]) + bo[0];
            }
            {
                float inv = __fdividef(1.f, (float)(p + 1));
                size_t wbase = (size_t)64 * nq;
#pragma unroll
                for (int c = 0; c < 4; ++c) {
                    int r = 4 * g_ + c;
                    out[wbase + ((size_t)(b0 + r) * nq + q) * 64 + d_] =
                        __fdividef(gacc[c], sh_l[r]) * inv;
                }
            }
        }
        __syncthreads();   // protect sh_l/sh_betaP reads before next segment reinit
    } // segments
}

// ---------------- launch ----------------
extern "C" void kernel_launch(void* const* d_in, const int* in_sizes, int n_in,
                              void* d_out, int out_size) {
    const float* x     = (const float*)d_in[0];
    const float* W_emb = (const float*)d_in[1];
    const float* b_emb = (const float*)d_in[2];
    const float* Wi_a  = (const float*)d_in[3];
    const float* Wh_a  = (const float*)d_in[4];
    const float* bi_a  = (const float*)d_in[5];
    const float* bh_a  = (const float*)d_in[6];
    const float* Wi_b  = (const float*)d_in[7];
    const float* Wh_b  = (const float*)d_in[8];
    const float* bi_b  = (const float*)d_in[9];
    const float* bh_b  = (const float*)d_in[10];
    const float* Wa    = (const float*)d_in[11];
    const float* ba    = (const float*)d_in[12];
    const float* Wb    = (const float*)d_in[13];
    const float* bb    = (const float*)d_in[14];
    const float* Wo    = (const float*)d_in[15];
    const float* bo    = (const float*)d_in[16];
    float* out = (float*)d_out;

    int nq = out_size / (64 * 65);   // = T - 2 - short = 60

    prep_transpose<<<96, 256>>>(Wh_a, Wh_b, Wi_a, Wi_b, Wb, W_emb, Wo);
    emb_kernel<<<Tn * Bn, 128>>>(x, b_emb);
    gi_kernel<<<Tn * Bn, 256>>>(bi_a, bi_b);
    retain_main<<<128, 256>>>(x, bh_a, bh_b, Wa, ba, bb, Wo, bo, nq, out);
}

// round 5
// speedup vs baseline: 1.7021x; 1.7021x over previous
#include <cuda_runtime.h>
#include <cstdint>

#define Bn 64
#define Tn 64
#define Dn 64
#define Pn 63
typedef unsigned long long ull;

// ---------------- device scratch ----------------
__device__ float g_emb[Tn * Bn * 128];            // [t][b][e]
__device__ ull   g_giP[64 * 2 * 32 * 3 * 128];    // [t][gru][rpg][gate][k] rows packed in pairs
__device__ float g_WiaT[128 * 384];               // [e][u]
__device__ float g_WibT[128 * 384];
__device__ float g_WhPack[128 * 768];             // per i: [gru][ (wr,wz) x128 pairs | wn x128 ]
__device__ float g_WbT[128 * 128];                // [i][e]
__device__ float g_WembT[64 * 128];               // [d][e]
__device__ float g_WoWemb[128 * 64];              // [e][d]

// ---------------- f32x2 helpers ----------------
__device__ __forceinline__ ull pack2(float x, float y) {
    ull r; asm("mov.b64 %0, {%1,%2};" : "=l"(r) : "f"(x), "f"(y)); return r;
}
__device__ __forceinline__ float2 unpack2(ull v) {
    float2 r; asm("mov.b64 {%0,%1}, %2;" : "=f"(r.x), "=f"(r.y) : "l"(v)); return r;
}
__device__ __forceinline__ ull fma2(ull a, ull b, ull c) {
    ull d; asm("fma.rn.f32x2 %0, %1, %2, %3;" : "=l"(d) : "l"(a), "l"(b), "l"(c)); return d;
}
__device__ __forceinline__ float sigmoidf_(float v) {
    return __fdividef(1.f, 1.f + __expf(-v));
}
__device__ __forceinline__ float tanhfast(float v) {
    float e = __expf(2.f * v);
    return 1.f - __fdividef(2.f, e + 1.f);
}
__device__ __forceinline__ float gru_step(float ir, float iz, float in_,
                                          float hr, float hz, float hn, float h) {
    float r = sigmoidf_(ir + hr);
    float z = sigmoidf_(iz + hz);
    float n = tanhfast(in_ + r * hn);
    return n + z * (h - n);
}

// ---------------- cp.async helpers ----------------
__device__ __forceinline__ void cp16(uint32_t dst, const void* src) {
    asm volatile("cp.async.cg.shared.global [%0], [%1], 16;\n" :: "r"(dst), "l"(src));
}
__device__ __forceinline__ void cp_commit() {
    asm volatile("cp.async.commit_group;\n" ::: "memory");
}
__device__ __forceinline__ void cp_wait1() {
    asm volatile("cp.async.wait_group 1;\n" ::: "memory");
}

// ---------------- prep ----------------
__global__ void prep_transpose(const float* __restrict__ Wh_a,
                               const float* __restrict__ Wh_b,
                               const float* __restrict__ Wi_a,
                               const float* __restrict__ Wi_b,
                               const float* __restrict__ Wb,
                               const float* __restrict__ W_emb,
                               const float* __restrict__ Wo) {
    int idx = blockIdx.x * blockDim.x + threadIdx.x;
    int stride = gridDim.x * blockDim.x;
    for (int n = idx; n < 128 * 384; n += stride) {
        int u = n % 384, i = n / 384;
        g_WiaT[n] = Wi_a[u * 128 + i];
        g_WibT[n] = Wi_b[u * 128 + i];
    }
    // WhPack: per (i, gru, k) write (wr,wz) pair + wn
    for (int n = idx; n < 128 * 256; n += stride) {
        int i = n >> 8;
        int rem = n & 255;
        int gru = rem >> 7;
        int k = rem & 127;
        const float* Wh = gru ? Wh_b : Wh_a;
        float wr = Wh[(0   + k) * 128 + i];
        float wz = Wh[(128 + k) * 128 + i];
        float wn = Wh[(256 + k) * 128 + i];
        int base = i * 768 + gru * 384;
        g_WhPack[base + 2 * k]     = wr;
        g_WhPack[base + 2 * k + 1] = wz;
        g_WhPack[base + 256 + k]   = wn;
    }
    for (int n = idx; n < 128 * 128; n += stride) {
        int e = n % 128, i = n / 128;
        g_WbT[n] = Wb[e * 128 + i];
    }
    for (int n = idx; n < 64 * 128; n += stride) {
        int e = n % 128, d = n / 128;
        g_WembT[n] = W_emb[e * 64 + d];
    }
    for (int n = idx; n < 128 * 64; n += stride) {
        int d = n % 64, e = n / 64;
        g_WoWemb[n] = Wo[e] * W_emb[e * 64 + d];
    }
}

// ---------------- emb ----------------
__global__ void emb_kernel(const float* __restrict__ x, const float* __restrict__ b_emb) {
    __shared__ float xs[64];
    int tb = blockIdx.x;
    int t_ = tb >> 6, b = tb & 63;
    int e = threadIdx.x;
    if (e < 64) xs[e] = x[((size_t)b * Tn + t_) * Dn + e];
    __syncthreads();
    float acc = 0.f;
#pragma unroll 8
    for (int d = 0; d < 64; ++d) acc = fmaf(g_WembT[d * 128 + e], xs[d], acc);
    g_emb[(size_t)tb * 128 + e] = acc + b_emb[e];
}

// ---------------- gi (packed row-pair output) ----------------
__global__ void gi_kernel(const float* __restrict__ bi_a, const float* __restrict__ bi_b) {
    __shared__ float es[128];
    int tb = blockIdx.x;
    int t_ = tb >> 6, b = tb & 63;
    int t = threadIdx.x;
    if (t < 128) es[t] = g_emb[(size_t)tb * 128 + t];
    __syncthreads();
    float* gf = (float*)g_giP;
    for (int u = t; u < 768; u += 256) {
        const float* WT;
        const float* bi;
        int gru, uu;
        if (u < 384) { WT = g_WiaT; bi = bi_a; gru = 0; uu = u; }
        else         { WT = g_WibT; bi = bi_b; gru = 1; uu = u - 384; }
        float acc = 0.f;
#pragma unroll 8
        for (int e = 0; e < 128; ++e) acc = fmaf(WT[e * 384 + uu], es[e], acc);
        int gate = uu >> 7, k = uu & 127;
        size_t ullIdx = (((size_t)(t_ * 2 + gru) * 32 + (b >> 1)) * 3 + gate) * 128 + k;
        gf[ullIdx * 2 + (b & 1)] = acc + bi[uu];
    }
}

// ---------------- main persistent kernel ----------------
// grid 128 = 32 prefix-pairs x 4 batch-chunks of 16 rows; dynamic smem ring of weights.
#define SMW_BYTES  147456              // 3 slots x 48KB
#define SHH_OFF    147456              // ull [2][2][128][8] = 32768
#define BETA_OFF   180224              // ull [8][128] = 8192
#define SCAL_OFF   188416              // 5 x 16 floats
#define SMEM_TOTAL 188800

__global__ __launch_bounds__(256, 1) void retain_main(
    const float* __restrict__ x,
    const float* __restrict__ bh_a, const float* __restrict__ bh_b,
    const float* __restrict__ Wa, const float* __restrict__ ba,
    const float* __restrict__ bb, const float* __restrict__ Wo,
    const float* __restrict__ bo, int nq, float* __restrict__ out) {

    extern __shared__ char dsm[];
    float* smw = (float*)dsm;
    ull (*sh_h)[2][128][8] = (ull (*)[2][128][8])(dsm + SHH_OFF);
    ull (*sh_betaP)[128]   = (ull (*)[128])(dsm + BETA_OFF);
    float* sh_preA  = (float*)(dsm + SCAL_OFF);
    float* sh_scale = sh_preA + 16;
    float* sh_w     = sh_preA + 32;
    float* sh_m     = sh_preA + 48;
    float* sh_l     = sh_preA + 64;

    const int t = threadIdx.x;
    const int pb = blockIdx.x >> 2;
    const int b0 = (blockIdx.x & 3) * 16;

    const int gru = t >> 7;
    const int k = t & 127;
    const int d_ = t & 63;
    const int g_ = t >> 6;
    const int row16 = t >> 4;
    const int l16 = t & 15;

    const float* giT_bh = gru ? bh_b : bh_a;
    const float bhr = giT_bh[k], bhz = giT_bh[128 + k], bhn = giT_bh[256 + k];
    const float ba0 = ba[0], bbk = bb[k];
    const int base = Pn - nq;

    const bool seg2 = (pb < 31) && (pb >= base);
    const int totalSteps = (63 - pb) + (seg2 ? pb + 1 : 0);
    const int totalTiles = 11 * totalSteps;

    uint32_t smw32 = (uint32_t)__cvta_generic_to_shared(dsm);

    int issIdx = 0, issM = 0, issSlot = 0, consSlot = 0;

#define ISSUE_ONE() do {                                                        \
        const char* _src; int _bytes;                                           \
        if (issM < 8)       { _src = (const char*)g_WhPack + issM * 49152; _bytes = 49152; } \
        else if (issM == 8) { _src = (const char*)g_WbT;            _bytes = 32768; } \
        else if (issM == 9) { _src = (const char*)g_WbT + 32768;    _bytes = 32768; } \
        else                { _src = (const char*)g_WoWemb;         _bytes = 32768; } \
        uint32_t _d = smw32 + (uint32_t)issSlot * 49152u;                        \
        for (int _o = t * 16; _o < _bytes; _o += 4096) cp16(_d + _o, _src + _o); \
        cp_commit();                                                             \
        ++issIdx; if (++issM == 11) issM = 0; if (++issSlot == 3) issSlot = 0;   \
    } while (0)

#define ADVANCE() do {                                                          \
        cp_wait1(); __syncthreads();                                            \
        if (issIdx < totalTiles) { ISSUE_ONE(); }                               \
    } while (0)

    // prologue: 2 tiles in flight
    ISSUE_ONE();
    ISSUE_ONE();

    for (int seg = 0; seg < 2; ++seg) {
        const int p = seg ? pb : 62 - pb;
        if (seg && !seg2) break;

        for (int n = t; n < 2 * 128 * 8; n += 256)
            ((ull*)sh_h[0])[n] = 0ull;
        if (t < 16) { sh_m[t] = -1e30f; sh_l[t] = 0.f; }
        float cacc[8] = {0.f, 0.f, 0.f, 0.f, 0.f, 0.f, 0.f, 0.f};
        float gacc[4] = {0.f, 0.f, 0.f, 0.f};
        __syncthreads();

        for (int s = 0; s <= p; ++s) {
            const int j = p - s;
            const int cb = s & 1;
            const ull (*cur)[8]  = sh_h[cb][gru];
            ull (*nxtg)[8]       = sh_h[cb ^ 1][gru];
            const ull (*nxtA)[8] = sh_h[cb ^ 1][0];
            const ull (*nxtB)[8] = sh_h[cb ^ 1][1];

            // ---- phase 1: gh = h @ Wh^T (weights from smem ring) ----
            ull aR[8], aZ[8], aN[8];
#pragma unroll
            for (int r = 0; r < 8; ++r) { aR[r] = 0ull; aZ[r] = 0ull; aN[r] = 0ull; }

#pragma unroll 1
            for (int tl = 0; tl < 8; ++tl) {
                ADVANCE();
                const float* wb = smw + (size_t)consSlot * 12288;
                consSlot = (consSlot + 1) == 3 ? 0 : consSlot + 1;
                const int ib = tl * 16;
#pragma unroll 4
                for (int ii = 0; ii < 16; ++ii) {
                    const float* wrow = wb + ii * 768 + gru * 384;
                    float2 rz = *(const float2*)(wrow + 2 * k);
                    float wn = wrow[256 + k];
                    ull wr2 = pack2(rz.x, rz.x), wz2 = pack2(rz.y, rz.y), wn2 = pack2(wn, wn);
                    const ulonglong2* hp = reinterpret_cast<const ulonglong2*>(cur[ib + ii]);
                    ulonglong2 hA = hp[0], hB = hp[1], hC = hp[2], hD = hp[3];
                    aR[0] = fma2(wr2, hA.x, aR[0]); aZ[0] = fma2(wz2, hA.x, aZ[0]); aN[0] = fma2(wn2, hA.x, aN[0]);
                    aR[1] = fma2(wr2, hA.y, aR[1]); aZ[1] = fma2(wz2, hA.y, aZ[1]); aN[1] = fma2(wn2, hA.y, aN[1]);
                    aR[2] = fma2(wr2, hB.x, aR[2]); aZ[2] = fma2(wz2, hB.x, aZ[2]); aN[2] = fma2(wn2, hB.x, aN[2]);
                    aR[3] = fma2(wr2, hB.y, aR[3]); aZ[3] = fma2(wz2, hB.y, aZ[3]); aN[3] = fma2(wn2, hB.y, aN[3]);
                    aR[4] = fma2(wr2, hC.x, aR[4]); aZ[4] = fma2(wz2, hC.x, aZ[4]); aN[4] = fma2(wn2, hC.x, aN[4]);
                    aR[5] = fma2(wr2, hC.y, aR[5]); aZ[5] = fma2(wz2, hC.y, aZ[5]); aN[5] = fma2(wn2, hC.y, aN[5]);
                    aR[6] = fma2(wr2, hD.x, aR[6]); aZ[6] = fma2(wz2, hD.x, aZ[6]); aN[6] = fma2(wn2, hD.x, aN[6]);
                    aR[7] = fma2(wr2, hD.y, aR[7]); aZ[7] = fma2(wz2, hD.y, aZ[7]); aN[7] = fma2(wn2, hD.y, aN[7]);
                }
            }

            // ---- phase 2: GRU cell update (gi packed LDG.64) ----
            {
                const ull* gbase = g_giP + ((size_t)(j * 2 + gru) * 96 + (b0 >> 1) * 3) * 128 + k;
#pragma unroll
                for (int r = 0; r < 8; ++r) {
                    float2 gr = unpack2(gbase[(size_t)r * 384]);
                    float2 gz = unpack2(gbase[(size_t)r * 384 + 128]);
                    float2 gn = unpack2(gbase[(size_t)r * 384 + 256]);
                    float2 hr = unpack2(aR[r]);
                    float2 hz = unpack2(aZ[r]);
                    float2 hn = unpack2(aN[r]);
                    float2 ho = unpack2(cur[k][r]);
                    float hx = gru_step(gr.x, gz.x, gn.x,
                                        hr.x + bhr, hz.x + bhz, hn.x + bhn, ho.x);
                    float hy = gru_step(gr.y, gz.y, gn.y,
                                        hr.y + bhr, hz.y + bhz, hn.y + bhn, ho.y);
                    nxtg[k][r] = pack2(hx, hy);
                }
            }

            // ---- phase 3a: beta GEMM (tiles 8,9) + preA ----
            ull bacc[4] = {0ull, 0ull, 0ull, 0ull};
            const int rpo = 4 * gru;
            {
                ADVANCE();   // tile 8: WbT rows i<64 (sync also orders phase-2 writes)
                const float* wbb = smw + (size_t)consSlot * 12288;
                consSlot = (consSlot + 1) == 3 ? 0 : consSlot + 1;
#pragma unroll 2
                for (int i = 0; i < 64; ++i) {
                    float wv = wbb[i * 128 + k];
                    ull wb2 = pack2(wv, wv);
                    const ulonglong2* hp = reinterpret_cast<const ulonglong2*>(nxtB[i] + rpo);
                    ulonglong2 hA = hp[0], hB = hp[1];
                    bacc[0] = fma2(wb2, hA.x, bacc[0]);
                    bacc[1] = fma2(wb2, hA.y, bacc[1]);
                    bacc[2] = fma2(wb2, hB.x, bacc[2]);
                    bacc[3] = fma2(wb2, hB.y, bacc[3]);
                }
            }
            {   // preA (reads nxtA, ordered by tile-8 sync)
                float part = 0.f;
#pragma unroll
                for (int ii = 0; ii < 8; ++ii) {
                    int i = l16 + 16 * ii;
                    float2 hv = unpack2(nxtA[i][row16 >> 1]);
                    part = fmaf(Wa[i], (row16 & 1) ? hv.y : hv.x, part);
                }
#pragma unroll
                for (int o = 8; o; o >>= 1)
                    part += __shfl_xor_sync(0xffffffffu, part, o, 16);
                if (l16 == 0) sh_preA[row16] = fmaf(0.5f, part, ba0);
            }
            float lbeta[8];
            {
                ADVANCE();   // tile 9: WbT rows i>=64
                const float* wbb = smw + (size_t)consSlot * 12288;
                consSlot = (consSlot + 1) == 3 ? 0 : consSlot + 1;
#pragma unroll 2
                for (int i = 0; i < 64; ++i) {
                    float wv = wbb[i * 128 + k];
                    ull wb2 = pack2(wv, wv);
                    const ulonglong2* hp = reinterpret_cast<const ulonglong2*>(nxtB[64 + i] + rpo);
                    ulonglong2 hA = hp[0], hB = hp[1];
                    bacc[0] = fma2(wb2, hA.x, bacc[0]);
                    bacc[1] = fma2(wb2, hA.y, bacc[1]);
                    bacc[2] = fma2(wb2, hB.x, bacc[2]);
                    bacc[3] = fma2(wb2, hB.y, bacc[3]);
                }
#pragma unroll
                for (int c = 0; c < 4; ++c) {
                    float2 v = unpack2(bacc[c]);
                    float bx = tanhfast(fmaf(0.5f, v.x, bbk));
                    float by = tanhfast(fmaf(0.5f, v.y, bbk));
                    lbeta[2 * c] = bx;
                    lbeta[2 * c + 1] = by;
                    sh_betaP[rpo + c][k] = pack2(bx, by);
                }
            }

            // ---- phase 3b: softmax scalars + e_chain (tile 10) ----
            float ech[4];
            {
                ADVANCE();   // tile 10: WoWemb (sync orders betaP + preA writes)
                const float* wco = smw + (size_t)consSlot * 12288;
                consSlot = (consSlot + 1) == 3 ? 0 : consSlot + 1;
                if (t < 16) {
                    float pa = sh_preA[t], mo = sh_m[t];
                    float mn = fmaxf(mo, pa);
                    float sc = __expf(mo - mn);
                    float w = __expf(pa - mn);
                    sh_scale[t] = sc;
                    sh_w[t] = w;
                    sh_l[t] = sh_l[t] * sc + w;
                    sh_m[t] = mn;
                }
                ull ea0 = 0ull, ea1 = 0ull;
                const ull* bp0 = sh_betaP[2 * g_];
                const ull* bp1 = sh_betaP[2 * g_ + 1];
                const float* wc0 = wco + d_;
#pragma unroll 2
                for (int e = 0; e < 128; ++e) {
                    float wc = wc0[e * 64];
                    ull wc2 = pack2(wc, wc);
                    ea0 = fma2(wc2, bp0[e], ea0);
                    ea1 = fma2(wc2, bp1[e], ea1);
                }
                float2 a = unpack2(ea0), b = unpack2(ea1);
                ech[0] = a.x; ech[1] = a.y; ech[2] = b.x; ech[3] = b.y;
            }
            __syncthreads();   // order sh_scale/sh_w writes before phase 3c

            // ---- phase 3c: accumulator updates ----
            {
                const float* eb = g_emb + ((size_t)(j * 64 + b0 + 8 * gru)) * 128 + k;
#pragma unroll
                for (int c = 0; c < 8; ++c) {
                    int r = 8 * gru + c;
                    cacc[c] = fmaf(cacc[c], sh_scale[r],
                                   sh_w[r] * lbeta[c] * eb[(size_t)c * 128]);
                }
#pragma unroll
                for (int c = 0; c < 4; ++c) {
                    int r = 4 * g_ + c;
                    float xv = x[((size_t)(b0 + r) * Tn + j) * Dn + d_];
                    gacc[c] = fmaf(gacc[c], sh_scale[r], sh_w[r] * ech[c] * xv);
                }
            }
        } // steps

        // ---- finalize this trajectory ----
        __syncthreads();
        if (p >= base) {
            const int q = p - base;
#pragma unroll
            for (int c = 0; c < 4; ++c)
                sh_betaP[4 * gru + c][k] = pack2(cacc[2 * c], cacc[2 * c + 1]);
            __syncthreads();

            if (t < 16) {
                float sum = 0.f;
                const ull* Crow = sh_betaP[t >> 1];
                const bool hi = (t & 1);
#pragma unroll 8
                for (int e = 0; e < 128; ++e) {
                    float2 v = unpack2(Crow[e]);
                    sum = fmaf(Wo[e], hi ? v.y : v.x, sum);
                }
                out[(size_t)(b0 + t) * nq + q] = __fdividef(sum, sh_l[t]) + bo[0];
            }
            {
                float inv = __fdividef(1.f, (float)(p + 1));
                size_t wbase = (size_t)64 * nq;
#pragma unroll
                for (int c = 0; c < 4; ++c) {
                    int r = 4 * g_ + c;
                    out[wbase + ((size_t)(b0 + r) * nq + q) * 64 + d_] =
                        __fdividef(gacc[c], sh_l[r]) * inv;
                }
            }
        }
        __syncthreads();
    } // segments
#undef ADVANCE
#undef ISSUE_ONE
}

// ---------------- launch ----------------
extern "C" void kernel_launch(void* const* d_in, const int* in_sizes, int n_in,
                              void* d_out, int out_size) {
    const float* x     = (const float*)d_in[0];
    const float* W_emb = (const float*)d_in[1];
    const float* b_emb = (const float*)d_in[2];
    const float* Wi_a  = (const float*)d_in[3];
    const float* Wh_a  = (const float*)d_in[4];
    const float* bi_a  = (const float*)d_in[5];
    const float* bh_a  = (const float*)d_in[6];
    const float* Wi_b  = (const float*)d_in[7];
    const float* Wh_b  = (const float*)d_in[8];
    const float* bi_b  = (const float*)d_in[9];
    const float* bh_b  = (const float*)d_in[10];
    const float* Wa    = (const float*)d_in[11];
    const float* ba    = (const float*)d_in[12];
    const float* Wb    = (const float*)d_in[13];
    const float* bb    = (const float*)d_in[14];
    const float* Wo    = (const float*)d_in[15];
    const float* bo    = (const float*)d_in[16];
    float* out = (float*)d_out;

    int nq = out_size / (64 * 65);   // = T - 2 - short = 60

    static int smem_set = 0;
    if (!smem_set) {
        cudaFuncSetAttribute(retain_main,
                             cudaFuncAttributeMaxDynamicSharedMemorySize, SMEM_TOTAL);
        smem_set = 1;
    }

    prep_transpose<<<96, 256>>>(Wh_a, Wh_b, Wi_a, Wi_b, Wb, W_emb, Wo);
    emb_kernel<<<Tn * Bn, 128>>>(x, b_emb);
    gi_kernel<<<Tn * Bn, 256>>>(bi_a, bi_b);
    retain_main<<<128, 256, SMEM_TOTAL>>>(x, bh_a, bh_b, Wa, ba, bb, Wo, bo, nq, out);
}